// round 6
// baseline (speedup 1.0000x reference)
#include <cuda_runtime.h>
#include <math.h>

#define BB   128
#define VV   128000
#define NV4  (VV/4)
#define TPB  1024
#define NB   256
#define CAND_MAX 5120

// monotonic float -> ordered uint32
__device__ __forceinline__ unsigned f2ord(float f) {
    unsigned u = __float_as_uint(f);
    return (u & 0x80000000u) ? ~u : (u | 0x80000000u);
}
// inverse (floor decode); NaN-zone keys fall out naturally:
// low zone decodes to -inf-ish/-NaN (compare keeps all after -inf special),
// high zone decodes to +NaN (compare keeps none) -> bisection self-corrects.
__device__ __forceinline__ float ord2f_floor(unsigned o) {
    if (o <= 0x007FFFFFu) return -__int_as_float(0x7f800000); // -inf: take all
    return (o & 0x80000000u) ? __uint_as_float(o ^ 0x80000000u)
                             : __uint_as_float(~o);
}

__device__ float blk_excl_scan(float v, float* tmp) {
    __syncthreads();
    int lane = threadIdx.x & 31, w = threadIdx.x >> 5;
    float x = v;
    #pragma unroll
    for (int o = 1; o < 32; o <<= 1) {
        float y = __shfl_up_sync(0xffffffffu, x, o);
        if (lane >= o) x += y;
    }
    if (lane == 31) tmp[w] = x;
    __syncthreads();
    if (w == 0) {
        float s = tmp[lane];
        #pragma unroll
        for (int o = 1; o < 32; o <<= 1) {
            float y = __shfl_up_sync(0xffffffffu, s, o);
            if (lane >= o) s += y;
        }
        tmp[lane] = s;
    }
    __syncthreads();
    float pre = (w > 0) ? tmp[w - 1] : 0.0f;
    return pre + x - v;
}

__device__ float blk_reduce_sum(float v, float* tmp) {
    __syncthreads();
    int lane = threadIdx.x & 31, w = threadIdx.x >> 5;
    #pragma unroll
    for (int o = 16; o; o >>= 1) v += __shfl_xor_sync(0xffffffffu, v, o);
    if (lane == 0) tmp[w] = v;
    __syncthreads();
    if (w == 0) {
        float x = tmp[lane];
        #pragma unroll
        for (int o = 16; o; o >>= 1) x += __shfl_xor_sync(0xffffffffu, x, o);
        if (lane == 0) tmp[0] = x;
    }
    __syncthreads();
    return tmp[0];
}

__device__ float blk_reduce_max(float v, float* tmp) {
    __syncthreads();
    int lane = threadIdx.x & 31, w = threadIdx.x >> 5;
    #pragma unroll
    for (int o = 16; o; o >>= 1) v = fmaxf(v, __shfl_xor_sync(0xffffffffu, v, o));
    if (lane == 0) tmp[w] = v;
    __syncthreads();
    if (w == 0) {
        float x = tmp[lane];
        #pragma unroll
        for (int o = 16; o; o >>= 1) x = fmaxf(x, __shfl_xor_sync(0xffffffffu, x, o));
        if (lane == 0) tmp[0] = x;
    }
    __syncthreads();
    return tmp[0];
}

struct CrossRes { int bin; float above; bool found; };

// 256-bin descending crossing: find bin c with cumAbove < target <= cumAbove+w[c]
__device__ CrossRes find_crossing256(const float* wgt, float target, float* scanTmp,
                                     int* sh_r, int* sh_b, float* sh_c) {
    __syncthreads();
    int t = threadIdx.x;
    float s = (t < NB) ? wgt[NB - 1 - t] : 0.f;
    float P = blk_excl_scan(s, scanTmp);
    if (t == 0) *sh_r = 0x7fffffff;
    __syncthreads();
    if (t < NB) {
        if (P < target && P + s >= target) atomicMin(sh_r, t);
    }
    __syncthreads();
    int fr = *sh_r;
    if (fr != 0x7fffffff && t == fr) { *sh_b = NB - 1 - t; *sh_c = P; }
    __syncthreads();
    CrossRes res;
    res.found = (fr != 0x7fffffff);
    res.bin = res.found ? *sh_b : 0;
    res.above = res.found ? *sh_c : 0.f;
    return res;
}

__global__ void __launch_bounds__(TPB, 1)
topk_topp_sample_kernel(const float* __restrict__ logits,
                        const int*   __restrict__ karr,
                        const float* __restrict__ parr,
                        const float* __restrict__ qarr,
                        float* __restrict__ out_ids,
                        float* __restrict__ out_probs)
{
    __shared__ float cand[CAND_MAX];      // 20 KB
    __shared__ int   candIdx[CAND_MAX];   // 20 KB
    __shared__ float h8[NB];              // 1 KB
    __shared__ float scanTmp[32];
    __shared__ float redTmp[32];
    __shared__ int   shr; __shared__ int shb; __shared__ float shc;
    __shared__ int   shn;
    __shared__ float argV[32]; __shared__ int argI[32];

    const int row = blockIdx.x;
    const int t = threadIdx.x;
    const int lane = t & 31, warp = t >> 5;
    const float* lg = logits + (long long)row * VV;
    const float* qr = qarr   + (long long)row * VV;
    float* pro = out_probs + (long long)row * VV;
    const int   k = karr[row];
    const float p = parr[row];

    const float4* lg4 = reinterpret_cast<const float4*>(lg);

    // ---- Phase A: speculative-floor compaction with key-space bisection ----
    unsigned loK = 0u, hiK = 0xFFFFFFFFu, fK = 0xC0000000u;  // f2ord(2.0f)
    int n = 0;
    for (int iter = 0; iter < 12; iter++) {
        if (t == 0) shn = 0;
        __syncthreads();
        const float ffloor = ord2f_floor(fK);
        for (int i = t; i < NV4; i += TPB) {
            float4 v = lg4[i];
            float xs[4] = {v.x, v.y, v.z, v.w};
            float loc[4]; int li[4]; int cnt = 0;
            #pragma unroll
            for (int j = 0; j < 4; j++)
                if (xs[j] >= ffloor) { loc[cnt] = xs[j]; li[cnt] = i * 4 + j; cnt++; }
            if (cnt) {
                int base = atomicAdd(&shn, cnt);
                #pragma unroll
                for (int c = 0; c < 4; c++)
                    if (c < cnt && base + c < CAND_MAX) {
                        cand[base + c] = loc[c];
                        candIdx[base + c] = li[c];
                    }
            }
        }
        __syncthreads();
        n = shn;
        if (n >= k && n <= CAND_MAX) break;
        if (n > CAND_MAX) { loK = fK; fK = fK + ((hiK - fK) >> 1); }
        else              { hiK = fK; fK = loK + ((fK - loK) >> 1); }
        __syncthreads();
    }
    if (n > CAND_MAX) n = CAND_MAX;

    // ---- Row max from candidates (global max is in cand) ----
    float mx = -3.4e38f;
    for (int i = t; i < n; i += TPB) mx = fmaxf(mx, cand[i]);
    float M = blk_reduce_max(mx, redTmp);

    // ---- Exact top-k threshold: 4-level 8-bit count radix on candidates ----
    unsigned pfx = 0u;
    float target = (float)k;
    #pragma unroll
    for (int level = 0; level < 4; level++) {
        const int shift = 24 - 8 * level;
        __syncthreads();
        if (t < NB) h8[t] = 0.f;
        __syncthreads();
        for (int i = t; i < n; i += TPB) {
            unsigned ou = f2ord(cand[i]);
            if (level == 0 || (ou >> (shift + 8)) == pfx)
                atomicAdd(&h8[(ou >> shift) & 255u], 1.f);
        }
        CrossRes cr = find_crossing256(h8, target, scanTmp, &shr, &shb, &shc);
        target -= cr.above;
        pfx = (pfx << 8) | (unsigned)cr.bin;
    }
    const unsigned thr_ou = pfx;

    // ---- Z_k over top-k set ----
    float zs = 0.f;
    for (int i = t; i < n; i += TPB) {
        float x = cand[i];
        if (f2ord(x) >= thr_ou) zs += __expf(x - M);
    }
    float Zk = blk_reduce_sum(zs, redTmp);
    float T = p * Zk;

    // ---- Weighted 4-level 8-bit radix descent for top-p cutoff ----
    unsigned t_ou = thr_ou;
    {
        unsigned wp = 0u;
        float tgt = T;
        bool done = false;
        #pragma unroll
        for (int level = 0; level < 4; level++) {
            if (done) break;
            const int shift = 24 - 8 * level;
            __syncthreads();
            if (t < NB) h8[t] = 0.f;
            __syncthreads();
            for (int i = t; i < n; i += TPB) {
                float x = cand[i];
                unsigned ou = f2ord(x);
                if (ou >= thr_ou && (level == 0 || (ou >> (shift + 8)) == wp))
                    atomicAdd(&h8[(ou >> shift) & 255u], __expf(x - M));
            }
            CrossRes cr = find_crossing256(h8, tgt, scanTmp, &shr, &shb, &shc);
            if (!cr.found) {
                t_ou = (level == 0) ? thr_ou : (wp << (shift + 8));
                done = true;
            } else {
                tgt -= cr.above;
                wp = (wp << 8) | (unsigned)cr.bin;
                if (level == 3) t_ou = wp;
            }
        }
    }
    const unsigned f_ou = (t_ou > thr_ou) ? t_ou : thr_ou;
    const float ford = ord2f_floor(f_ou);

    // ---- Final normalizer ----
    float zf = 0.f;
    for (int i = t; i < n; i += TPB) {
        float x = cand[i];
        if (x >= ford) zf += __expf(x - M);
    }
    float Z = blk_reduce_sum(zf, redTmp);
    float invZ = 1.0f / Z;

    // ---- Phase E1: stream zeros into probs (write-only) ----
    float4* pr4 = reinterpret_cast<float4*>(pro);
    const float4 z4 = make_float4(0.f, 0.f, 0.f, 0.f);
    for (int i = t; i < NV4; i += TPB) pr4[i] = z4;
    __syncthreads();

    // ---- Phase E2: sparse scatter of kept probs + Gumbel-max argmax ----
    float bv = -1.f; int bi = 0x7fffffff;
    for (int i = t; i < n; i += TPB) {
        float x = cand[i];
        if (x >= ford) {
            int idx = candIdx[i];
            float prob = __expf(x - M) * invZ;
            pro[idx] = prob;
            float ratio = prob / (-__logf(qr[idx]));
            if (ratio > bv || (ratio == bv && idx < bi)) { bv = ratio; bi = idx; }
        }
    }
    #pragma unroll
    for (int o = 16; o; o >>= 1) {
        float ov = __shfl_down_sync(0xffffffffu, bv, o);
        int   oi = __shfl_down_sync(0xffffffffu, bi, o);
        if (ov > bv || (ov == bv && oi < bi)) { bv = ov; bi = oi; }
    }
    if (lane == 0) { argV[warp] = bv; argI[warp] = bi; }
    __syncthreads();
    if (warp == 0) {
        bv = argV[lane]; bi = argI[lane];
        #pragma unroll
        for (int o = 16; o; o >>= 1) {
            float ov = __shfl_down_sync(0xffffffffu, bv, o);
            int   oi = __shfl_down_sync(0xffffffffu, bi, o);
            if (ov > bv || (ov == bv && oi < bi)) { bv = ov; bi = oi; }
        }
        if (lane == 0) out_ids[row] = (float)bi;
    }
}

extern "C" void kernel_launch(void* const* d_in, const int* in_sizes, int n_in,
                              void* d_out, int out_size) {
    const float* logits = (const float*)d_in[0];
    const int*   k      = (const int*)  d_in[1];
    const float* p      = (const float*)d_in[2];
    const float* q      = (const float*)d_in[3];
    float* out = (float*)d_out;
    float* out_ids   = out;
    float* out_probs = out + BB;
    topk_topp_sample_kernel<<<BB, TPB>>>(logits, k, p, q, out_ids, out_probs);
}